// round 1
// baseline (speedup 1.0000x reference)
#include <cuda_runtime.h>

// Problem constants (fixed by the reference): B=2, S=2048, D=1024, H=16, HD=64
#define BB 2
#define SS 2048
#define DD 1024
#define HH 16
#define HDD 64
#define MROWS (BB * SS)   // 4096

// Scratch (allocation-free rule: __device__ globals)
__device__ float g_Q[BB * SS * DD];
__device__ float g_K[BB * SS * DD];
__device__ float g_V[BB * SS * DD];
__device__ float g_C[BB * SS * DD];

// ---------------------------------------------------------------------------
// SGEMM: C[M,N] = A[M,K] @ W[K,N] + bias[N]   (M=4096, N=K=1024 fixed)
// 128x128 block tile, BK=8, 256 threads, 8x8 per-thread microtile.
// ---------------------------------------------------------------------------
__global__ __launch_bounds__(256, 2)
void sgemm_bias(const float* __restrict__ A, const float* __restrict__ W,
                const float* __restrict__ bias, float* __restrict__ C)
{
    constexpr int K = 1024, N = 1024;
    __shared__ float As[8][128];   // As[k][m] (A tile transposed)
    __shared__ float Bs[8][128];   // Bs[k][n]

    const int tid = threadIdx.x;
    const int tx = tid & 15;       // col microtile index
    const int ty = tid >> 4;       // row microtile index
    const int rowBase = blockIdx.y * 128;
    const int colBase = blockIdx.x * 128;

    // A loading: one float4 per thread, 128 rows x 8 cols
    const int arow = tid >> 1;            // 0..127
    const int acol = (tid & 1) * 4;       // 0 or 4
    // B loading: one float4 per thread, 8 rows x 128 cols
    const int brow = tid >> 5;            // 0..7
    const int bcol = (tid & 31) * 4;      // 0..124

    const float* Ap = A + (size_t)(rowBase + arow) * K + acol;
    const float* Wp = W + (size_t)brow * N + colBase + bcol;

    float acc[8][8];
#pragma unroll
    for (int i = 0; i < 8; i++)
#pragma unroll
        for (int j = 0; j < 8; j++) acc[i][j] = 0.f;

    for (int k0 = 0; k0 < K; k0 += 8) {
        const float4 av = *(const float4*)(Ap + k0);
        const float4 bv = *(const float4*)(Wp + (size_t)k0 * N);
        __syncthreads();
        As[acol + 0][arow] = av.x;
        As[acol + 1][arow] = av.y;
        As[acol + 2][arow] = av.z;
        As[acol + 3][arow] = av.w;
        *(float4*)&Bs[brow][bcol] = bv;
        __syncthreads();
#pragma unroll
        for (int k = 0; k < 8; k++) {
            float a[8], b[8];
            *(float4*)&a[0] = *(const float4*)&As[k][ty * 8];
            *(float4*)&a[4] = *(const float4*)&As[k][ty * 8 + 4];
            *(float4*)&b[0] = *(const float4*)&Bs[k][tx * 8];
            *(float4*)&b[4] = *(const float4*)&Bs[k][tx * 8 + 4];
#pragma unroll
            for (int i = 0; i < 8; i++)
#pragma unroll
                for (int j = 0; j < 8; j++)
                    acc[i][j] = fmaf(a[i], b[j], acc[i][j]);
        }
    }

    float bb[8];
#pragma unroll
    for (int j = 0; j < 8; j++) bb[j] = bias[colBase + tx * 8 + j];
#pragma unroll
    for (int i = 0; i < 8; i++) {
        float* Cp = C + (size_t)(rowBase + ty * 8 + i) * N + colBase + tx * 8;
        float4 o0 = make_float4(acc[i][0] + bb[0], acc[i][1] + bb[1],
                                acc[i][2] + bb[2], acc[i][3] + bb[3]);
        float4 o1 = make_float4(acc[i][4] + bb[4], acc[i][5] + bb[5],
                                acc[i][6] + bb[6], acc[i][7] + bb[7]);
        *(float4*)Cp = o0;
        *(float4*)(Cp + 4) = o1;
    }
}

// ---------------------------------------------------------------------------
// Flash attention: one CTA per (b, h, 64-query tile). TQ=TK=64, HD=64.
// smem: Qt[64d][64q], Kt[64d][64k], Vs[64k][68hd-pad], Pt[64k][68q-pad]
// Score stage and PV stage are 4x4 register-tiled outer products.
// Online softmax over the full S=2048 key range.
// ---------------------------------------------------------------------------
#define ATT_SMEM_FLOATS (4096 + 4096 + 64*68 + 64*68 + 192)
#define ATT_SMEM_BYTES  (ATT_SMEM_FLOATS * 4)   // 68,352 B

__global__ __launch_bounds__(256, 1)
void attn_kernel()
{
    extern __shared__ float sm[];
    float* Qt = sm;                         // [64][64]  d-major
    float* Kt = sm + 4096;                  // [64][64]  d-major
    float* Vs = sm + 8192;                  // [64][68]  k-major (padded)
    float* Pt = sm + 8192 + 64 * 68;        // [64][68]  k rows, q cols (padded)
    float* m_s    = Pt + 64 * 68;           // [64] running max
    float* l_s    = m_s + 64;               // [64] running sum
    float* corr_s = l_s + 64;               // [64] rescale factor

    const int tid = threadIdx.x;
    const int b = blockIdx.z, h = blockIdx.y;
    const int q0g = blockIdx.x * 64;

    const float* Qg = g_Q + ((size_t)b * SS + q0g) * DD + h * HDD;
    const float* Kg = g_K + (size_t)b * SS * DD + h * HDD;
    const float* Vg = g_V + (size_t)b * SS * DD + h * HDD;

    // tile-load mapping: each thread moves 16 floats
    const int lq  = tid & 63;               // row within tile
    const int ld0 = (tid >> 6) * 16;        // 16-wide d chunk
    // V-load mapping
    const int vrow = tid >> 2;              // 0..63
    const int vd0  = (tid & 3) * 16;

    // compute mapping (both stages): 4 queries x 4 (keys | hd)
    const int tx = tid & 15, ty = tid >> 4;
    const int qq = tx * 4;                  // query sub-block
    const int kb = ty * 4;                  // key sub-block (score stage)
    const int hb = ty * 4;                  // hd sub-block (PV stage)

    // Load Q tile transposed, pre-scaled by 1/sqrt(HD)
#pragma unroll
    for (int c = 0; c < 4; c++) {
        const int d = ld0 + c * 4;
        const float4 v = *(const float4*)(Qg + (size_t)lq * DD + d);
        Qt[(d + 0) * 64 + lq] = v.x * 0.125f;
        Qt[(d + 1) * 64 + lq] = v.y * 0.125f;
        Qt[(d + 2) * 64 + lq] = v.z * 0.125f;
        Qt[(d + 3) * 64 + lq] = v.w * 0.125f;
    }
    if (tid < 64) { m_s[tid] = -1e30f; l_s[tid] = 0.f; }

    float acc[4][4];
#pragma unroll
    for (int i = 0; i < 4; i++)
#pragma unroll
        for (int j = 0; j < 4; j++) acc[i][j] = 0.f;

    __syncthreads();

    for (int kt = 0; kt < SS / 64; kt++) {
        const int kr = kt * 64;
        // K tile transposed
#pragma unroll
        for (int c = 0; c < 4; c++) {
            const int d = ld0 + c * 4;
            const float4 v = *(const float4*)(Kg + (size_t)(kr + lq) * DD + d);
            Kt[(d + 0) * 64 + lq] = v.x;
            Kt[(d + 1) * 64 + lq] = v.y;
            Kt[(d + 2) * 64 + lq] = v.z;
            Kt[(d + 3) * 64 + lq] = v.w;
        }
        // V tile natural (padded rows)
#pragma unroll
        for (int c = 0; c < 4; c++) {
            const int d = vd0 + c * 4;
            *(float4*)(Vs + vrow * 68 + d) =
                *(const float4*)(Vg + (size_t)(kr + vrow) * DD + d);
        }
        __syncthreads();

        // ---- scores: S[q][k] = sum_d Qt[d][q] * Kt[d][k] ----
        float s[4][4];
#pragma unroll
        for (int i = 0; i < 4; i++)
#pragma unroll
            for (int j = 0; j < 4; j++) s[i][j] = 0.f;
#pragma unroll 8
        for (int d = 0; d < 64; d++) {
            const float4 a  = *(const float4*)(Qt + d * 64 + qq);
            const float4 kv = *(const float4*)(Kt + d * 64 + kb);
            s[0][0] = fmaf(a.x, kv.x, s[0][0]); s[0][1] = fmaf(a.x, kv.y, s[0][1]);
            s[0][2] = fmaf(a.x, kv.z, s[0][2]); s[0][3] = fmaf(a.x, kv.w, s[0][3]);
            s[1][0] = fmaf(a.y, kv.x, s[1][0]); s[1][1] = fmaf(a.y, kv.y, s[1][1]);
            s[1][2] = fmaf(a.y, kv.z, s[1][2]); s[1][3] = fmaf(a.y, kv.w, s[1][3]);
            s[2][0] = fmaf(a.z, kv.x, s[2][0]); s[2][1] = fmaf(a.z, kv.y, s[2][1]);
            s[2][2] = fmaf(a.z, kv.z, s[2][2]); s[2][3] = fmaf(a.z, kv.w, s[2][3]);
            s[3][0] = fmaf(a.w, kv.x, s[3][0]); s[3][1] = fmaf(a.w, kv.y, s[3][1]);
            s[3][2] = fmaf(a.w, kv.z, s[3][2]); s[3][3] = fmaf(a.w, kv.w, s[3][3]);
        }
#pragma unroll
        for (int j = 0; j < 4; j++)
            *(float4*)(Pt + (kb + j) * 68 + qq) =
                make_float4(s[0][j], s[1][j], s[2][j], s[3][j]);
        __syncthreads();

        // ---- online softmax bookkeeping (one thread per query row) ----
        if (tid < 64) {
            const int q = tid;
            const float mo = m_s[q];
            float mx = mo;
#pragma unroll 8
            for (int kk = 0; kk < 64; kk++) mx = fmaxf(mx, Pt[kk * 68 + q]);
            const float corr = __expf(mo - mx);
            float l = l_s[q] * corr;
#pragma unroll 8
            for (int kk = 0; kk < 64; kk++) {
                const float p = __expf(Pt[kk * 68 + q] - mx);
                Pt[kk * 68 + q] = p;
                l += p;
            }
            m_s[q] = mx; l_s[q] = l; corr_s[q] = corr;
        }
        __syncthreads();

        // ---- rescale + PV: O[q][hd] += sum_k P[k][q] * V[k][hd] ----
        {
            const float c0 = corr_s[qq + 0], c1 = corr_s[qq + 1];
            const float c2 = corr_s[qq + 2], c3 = corr_s[qq + 3];
#pragma unroll
            for (int j = 0; j < 4; j++) {
                acc[0][j] *= c0; acc[1][j] *= c1;
                acc[2][j] *= c2; acc[3][j] *= c3;
            }
        }
#pragma unroll 8
        for (int kk = 0; kk < 64; kk++) {
            const float4 p = *(const float4*)(Pt + kk * 68 + qq);
            const float4 v = *(const float4*)(Vs + kk * 68 + hb);
            acc[0][0] = fmaf(p.x, v.x, acc[0][0]); acc[0][1] = fmaf(p.x, v.y, acc[0][1]);
            acc[0][2] = fmaf(p.x, v.z, acc[0][2]); acc[0][3] = fmaf(p.x, v.w, acc[0][3]);
            acc[1][0] = fmaf(p.y, v.x, acc[1][0]); acc[1][1] = fmaf(p.y, v.y, acc[1][1]);
            acc[1][2] = fmaf(p.y, v.z, acc[1][2]); acc[1][3] = fmaf(p.y, v.w, acc[1][3]);
            acc[2][0] = fmaf(p.z, v.x, acc[2][0]); acc[2][1] = fmaf(p.z, v.y, acc[2][1]);
            acc[2][2] = fmaf(p.z, v.z, acc[2][2]); acc[2][3] = fmaf(p.z, v.w, acc[2][3]);
            acc[3][0] = fmaf(p.w, v.x, acc[3][0]); acc[3][1] = fmaf(p.w, v.y, acc[3][1]);
            acc[3][2] = fmaf(p.w, v.z, acc[3][2]); acc[3][3] = fmaf(p.w, v.w, acc[3][3]);
        }
        __syncthreads();
    }

    // ---- finalize: divide by softmax denominator, write ctx[B,S,H*HD] ----
    float inv[4];
#pragma unroll
    for (int i = 0; i < 4; i++) inv[i] = 1.f / l_s[qq + i];

    float* Cg = g_C + ((size_t)b * SS + q0g) * DD + h * HDD;
#pragma unroll
    for (int i = 0; i < 4; i++) {
        const float4 o = make_float4(acc[i][0] * inv[i], acc[i][1] * inv[i],
                                     acc[i][2] * inv[i], acc[i][3] * inv[i]);
        *(float4*)(Cg + (size_t)(qq + i) * DD + hb) = o;
    }
}

// ---------------------------------------------------------------------------
// Launch: QKV GEMMs -> flash attention -> output projection
// ---------------------------------------------------------------------------
extern "C" void kernel_launch(void* const* d_in, const int* in_sizes, int n_in,
                              void* d_out, int out_size)
{
    (void)in_sizes; (void)n_in; (void)out_size;
    const float* x  = (const float*)d_in[0];
    const float* Wq = (const float*)d_in[1];
    const float* bq = (const float*)d_in[2];
    const float* Wk = (const float*)d_in[3];
    const float* bk = (const float*)d_in[4];
    const float* Wv = (const float*)d_in[5];
    const float* bv = (const float*)d_in[6];
    const float* Wo = (const float*)d_in[7];
    const float* bo = (const float*)d_in[8];
    float* out = (float*)d_out;

    float *qp, *kp, *vp, *cp;
    cudaGetSymbolAddress((void**)&qp, g_Q);
    cudaGetSymbolAddress((void**)&kp, g_K);
    cudaGetSymbolAddress((void**)&vp, g_V);
    cudaGetSymbolAddress((void**)&cp, g_C);

    cudaFuncSetAttribute(attn_kernel,
                         cudaFuncAttributeMaxDynamicSharedMemorySize,
                         ATT_SMEM_BYTES);

    const dim3 gblk(256);
    const dim3 ggrid(DD / 128, MROWS / 128);   // (8, 32)

    sgemm_bias<<<ggrid, gblk>>>(x, Wq, bq, qp);
    sgemm_bias<<<ggrid, gblk>>>(x, Wk, bk, kp);
    sgemm_bias<<<ggrid, gblk>>>(x, Wv, bv, vp);

    attn_kernel<<<dim3(SS / 64, HH, BB), 256, ATT_SMEM_BYTES>>>();

    sgemm_bias<<<ggrid, gblk>>>(cp, Wo, bo, out);
}

// round 2
// speedup vs baseline: 1.2648x; 1.2648x over previous
#include <cuda_runtime.h>
#include <cstdint>

// Problem constants (fixed by the reference): B=2, S=2048, D=1024, H=16, HD=64
#define BB 2
#define SS 2048
#define DD 1024
#define HH 16
#define HDD 64
#define MROWS (BB * SS)   // 4096

// Scratch (allocation-free rule: __device__ globals)
__device__ float g_Q[BB * SS * DD];
__device__ float g_K[BB * SS * DD];
__device__ float g_V[BB * SS * DD];
__device__ float g_C[BB * SS * DD];

// ---------------------------------------------------------------------------
// tf32 helpers
// ---------------------------------------------------------------------------
__device__ __forceinline__ uint32_t f2tf32(float x) {
    uint32_t u;
    asm("cvt.rna.tf32.f32 %0, %1;" : "=r"(u) : "f"(x));
    return u;
}

#define MMA_TF32(d, a, b)                                                    \
    asm volatile(                                                            \
        "mma.sync.aligned.m16n8k8.row.col.f32.tf32.tf32.f32 "                \
        "{%0,%1,%2,%3}, {%4,%5,%6,%7}, {%8,%9}, {%0,%1,%2,%3};"              \
        : "+f"((d)[0]), "+f"((d)[1]), "+f"((d)[2]), "+f"((d)[3])             \
        : "r"((a)[0]), "r"((a)[1]), "r"((a)[2]), "r"((a)[3]),                \
          "r"((b)[0]), "r"((b)[1]))

// ---------------------------------------------------------------------------
// tf32 tensor-core GEMM: C[M,N] = A[M,K] @ W[K,N] + bias[N]
// M=4096, N=K=1024. CTA tile 128x128, BK=16, 256 threads = 8 warps.
// Warp tile 64x32 = 4 m-tiles(16) x 4 n-tiles(8). mma m16n8k8 tf32.
//
// smem layout trick: within each k8 group, columns are stored in the
// permuted order pos(k) = 2*(k%4) + (k%8 >= 4), so that a thread's
// fragment pair (k = lane%4, k = lane%4+4) is two ADJACENT floats
// -> one LDS.64 per fragment pair.
// ---------------------------------------------------------------------------
#define AST 18   // padded row stride (16 + 2)

__global__ __launch_bounds__(256, 2)
void gemm_tf32(const float* __restrict__ A, const float* __restrict__ W,
               const float* __restrict__ bias, float* __restrict__ C)
{
    constexpr int K = 1024, N = 1024;
    __shared__ float As[128][AST];   // [m][k-perm]
    __shared__ float Bs[128][AST];   // [n][k-perm]  (W transposed)

    const int tid  = threadIdx.x;
    const int lane = tid & 31;
    const int wid  = tid >> 5;
    const int warp_m = wid >> 2;          // 0..1 -> 64 rows
    const int warp_n = wid & 3;           // 0..3 -> 32 cols
    const int rowBase = blockIdx.y * 128;
    const int colBase = blockIdx.x * 128;

    // A global-load mapping: 128 rows x 16 k -> 2 float4/thread (one k8 group)
    const int arow = tid >> 1;            // 0..127
    const int ag   = tid & 1;             // k8 group 0/1
    // B global-load mapping: 16 k-rows x 128 n -> 2 float4/thread
    const int brow = tid >> 4;            // k 0..15
    const int bcol = (tid & 15) * 4;      // n0 (second chunk at +64)

    const float* Ap = A + (size_t)(rowBase + arow) * K + ag * 8;
    const float* Wp = W + (size_t)brow * N + colBase + bcol;

    const int bg = brow >> 3;                                  // k8 group
    const int bp = 2 * (brow & 3) + (((brow & 7) >= 4) ? 1 : 0);
    const int bc = bg * 8 + bp;                                // permuted col

    float acc[4][4][4];
#pragma unroll
    for (int mt = 0; mt < 4; mt++)
#pragma unroll
        for (int nt = 0; nt < 4; nt++)
#pragma unroll
            for (int r = 0; r < 4; r++) acc[mt][nt][r] = 0.f;

    // ---- prologue: load tile 0 ----
    float4 a0v = *(const float4*)(Ap);
    float4 a1v = *(const float4*)(Ap + 4);
    float4 b0v = *(const float4*)(Wp);
    float4 b1v = *(const float4*)(Wp + 64);

    {
        const int c0 = ag * 8;
        As[arow][c0 + 0] = __uint_as_float(f2tf32(a0v.x));
        As[arow][c0 + 2] = __uint_as_float(f2tf32(a0v.y));
        As[arow][c0 + 4] = __uint_as_float(f2tf32(a0v.z));
        As[arow][c0 + 6] = __uint_as_float(f2tf32(a0v.w));
        As[arow][c0 + 1] = __uint_as_float(f2tf32(a1v.x));
        As[arow][c0 + 3] = __uint_as_float(f2tf32(a1v.y));
        As[arow][c0 + 5] = __uint_as_float(f2tf32(a1v.z));
        As[arow][c0 + 7] = __uint_as_float(f2tf32(a1v.w));
        Bs[bcol + 0][bc] = __uint_as_float(f2tf32(b0v.x));
        Bs[bcol + 1][bc] = __uint_as_float(f2tf32(b0v.y));
        Bs[bcol + 2][bc] = __uint_as_float(f2tf32(b0v.z));
        Bs[bcol + 3][bc] = __uint_as_float(f2tf32(b0v.w));
        Bs[bcol + 64][bc] = __uint_as_float(f2tf32(b1v.x));
        Bs[bcol + 65][bc] = __uint_as_float(f2tf32(b1v.y));
        Bs[bcol + 66][bc] = __uint_as_float(f2tf32(b1v.z));
        Bs[bcol + 67][bc] = __uint_as_float(f2tf32(b1v.w));
    }
    __syncthreads();

    const int niter = K / 16;   // 64
    for (int kt = 0; kt < niter; kt++) {
        // prefetch next tile into registers
        if (kt + 1 < niter) {
            const int ko = (kt + 1) * 16;
            a0v = *(const float4*)(Ap + ko);
            a1v = *(const float4*)(Ap + ko + 4);
            b0v = *(const float4*)(Wp + (size_t)ko * N);
            b1v = *(const float4*)(Wp + (size_t)ko * N + 64);
        }

        // ---- compute: two k8 steps ----
#pragma unroll
        for (int s = 0; s < 2; s++) {
            uint32_t af[4][4];
            uint32_t bf[4][2];
            const int kc = s * 8 + 2 * (lane & 3);
#pragma unroll
            for (int mt = 0; mt < 4; mt++) {
                const int r = warp_m * 64 + mt * 16 + (lane >> 2);
                const float2 lo = *(const float2*)&As[r][kc];
                const float2 hi = *(const float2*)&As[r + 8][kc];
                af[mt][0] = __float_as_uint(lo.x);
                af[mt][2] = __float_as_uint(lo.y);
                af[mt][1] = __float_as_uint(hi.x);
                af[mt][3] = __float_as_uint(hi.y);
            }
#pragma unroll
            for (int nt = 0; nt < 4; nt++) {
                const int n = warp_n * 32 + nt * 8 + (lane >> 2);
                const float2 bb = *(const float2*)&Bs[n][kc];
                bf[nt][0] = __float_as_uint(bb.x);
                bf[nt][1] = __float_as_uint(bb.y);
            }
#pragma unroll
            for (int mt = 0; mt < 4; mt++)
#pragma unroll
                for (int nt = 0; nt < 4; nt++)
                    MMA_TF32(acc[mt][nt], af[mt], bf[nt]);
        }

        if (kt + 1 < niter) {
            __syncthreads();
            const int c0 = ag * 8;
            As[arow][c0 + 0] = __uint_as_float(f2tf32(a0v.x));
            As[arow][c0 + 2] = __uint_as_float(f2tf32(a0v.y));
            As[arow][c0 + 4] = __uint_as_float(f2tf32(a0v.z));
            As[arow][c0 + 6] = __uint_as_float(f2tf32(a0v.w));
            As[arow][c0 + 1] = __uint_as_float(f2tf32(a1v.x));
            As[arow][c0 + 3] = __uint_as_float(f2tf32(a1v.y));
            As[arow][c0 + 5] = __uint_as_float(f2tf32(a1v.z));
            As[arow][c0 + 7] = __uint_as_float(f2tf32(a1v.w));
            Bs[bcol + 0][bc] = __uint_as_float(f2tf32(b0v.x));
            Bs[bcol + 1][bc] = __uint_as_float(f2tf32(b0v.y));
            Bs[bcol + 2][bc] = __uint_as_float(f2tf32(b0v.z));
            Bs[bcol + 3][bc] = __uint_as_float(f2tf32(b0v.w));
            Bs[bcol + 64][bc] = __uint_as_float(f2tf32(b1v.x));
            Bs[bcol + 65][bc] = __uint_as_float(f2tf32(b1v.y));
            Bs[bcol + 66][bc] = __uint_as_float(f2tf32(b1v.z));
            Bs[bcol + 67][bc] = __uint_as_float(f2tf32(b1v.w));
            __syncthreads();
        }
    }

    // ---- epilogue: bias + store ----
#pragma unroll
    for (int mt = 0; mt < 4; mt++) {
        const int r = rowBase + warp_m * 64 + mt * 16 + (lane >> 2);
#pragma unroll
        for (int nt = 0; nt < 4; nt++) {
            const int c = colBase + warp_n * 32 + nt * 8 + (lane & 3) * 2;
            const float bi0 = bias[c], bi1 = bias[c + 1];
            float2 o0 = make_float2(acc[mt][nt][0] + bi0, acc[mt][nt][1] + bi1);
            float2 o1 = make_float2(acc[mt][nt][2] + bi0, acc[mt][nt][3] + bi1);
            *(float2*)&C[(size_t)r * N + c] = o0;
            *(float2*)&C[(size_t)(r + 8) * N + c] = o1;
        }
    }
}

// ---------------------------------------------------------------------------
// Flash attention (unchanged from round 1): one CTA per (b, h, 64-query tile).
// ---------------------------------------------------------------------------
#define ATT_SMEM_FLOATS (4096 + 4096 + 64*68 + 64*68 + 192)
#define ATT_SMEM_BYTES  (ATT_SMEM_FLOATS * 4)   // 68,352 B

__global__ __launch_bounds__(256, 1)
void attn_kernel()
{
    extern __shared__ float sm[];
    float* Qt = sm;                         // [64][64]  d-major
    float* Kt = sm + 4096;                  // [64][64]  d-major
    float* Vs = sm + 8192;                  // [64][68]  k-major (padded)
    float* Pt = sm + 8192 + 64 * 68;        // [64][68]  k rows, q cols (padded)
    float* m_s    = Pt + 64 * 68;           // [64] running max
    float* l_s    = m_s + 64;               // [64] running sum
    float* corr_s = l_s + 64;               // [64] rescale factor

    const int tid = threadIdx.x;
    const int b = blockIdx.z, h = blockIdx.y;
    const int q0g = blockIdx.x * 64;

    const float* Qg = g_Q + ((size_t)b * SS + q0g) * DD + h * HDD;
    const float* Kg = g_K + (size_t)b * SS * DD + h * HDD;
    const float* Vg = g_V + (size_t)b * SS * DD + h * HDD;

    const int lq  = tid & 63;
    const int ld0 = (tid >> 6) * 16;
    const int vrow = tid >> 2;
    const int vd0  = (tid & 3) * 16;

    const int tx = tid & 15, ty = tid >> 4;
    const int qq = tx * 4;
    const int kb = ty * 4;
    const int hb = ty * 4;

#pragma unroll
    for (int c = 0; c < 4; c++) {
        const int d = ld0 + c * 4;
        const float4 v = *(const float4*)(Qg + (size_t)lq * DD + d);
        Qt[(d + 0) * 64 + lq] = v.x * 0.125f;
        Qt[(d + 1) * 64 + lq] = v.y * 0.125f;
        Qt[(d + 2) * 64 + lq] = v.z * 0.125f;
        Qt[(d + 3) * 64 + lq] = v.w * 0.125f;
    }
    if (tid < 64) { m_s[tid] = -1e30f; l_s[tid] = 0.f; }

    float acc[4][4];
#pragma unroll
    for (int i = 0; i < 4; i++)
#pragma unroll
        for (int j = 0; j < 4; j++) acc[i][j] = 0.f;

    __syncthreads();

    for (int kt = 0; kt < SS / 64; kt++) {
        const int kr = kt * 64;
#pragma unroll
        for (int c = 0; c < 4; c++) {
            const int d = ld0 + c * 4;
            const float4 v = *(const float4*)(Kg + (size_t)(kr + lq) * DD + d);
            Kt[(d + 0) * 64 + lq] = v.x;
            Kt[(d + 1) * 64 + lq] = v.y;
            Kt[(d + 2) * 64 + lq] = v.z;
            Kt[(d + 3) * 64 + lq] = v.w;
        }
#pragma unroll
        for (int c = 0; c < 4; c++) {
            const int d = vd0 + c * 4;
            *(float4*)(Vs + vrow * 68 + d) =
                *(const float4*)(Vg + (size_t)(kr + vrow) * DD + d);
        }
        __syncthreads();

        float s[4][4];
#pragma unroll
        for (int i = 0; i < 4; i++)
#pragma unroll
            for (int j = 0; j < 4; j++) s[i][j] = 0.f;
#pragma unroll 8
        for (int d = 0; d < 64; d++) {
            const float4 a  = *(const float4*)(Qt + d * 64 + qq);
            const float4 kv = *(const float4*)(Kt + d * 64 + kb);
            s[0][0] = fmaf(a.x, kv.x, s[0][0]); s[0][1] = fmaf(a.x, kv.y, s[0][1]);
            s[0][2] = fmaf(a.x, kv.z, s[0][2]); s[0][3] = fmaf(a.x, kv.w, s[0][3]);
            s[1][0] = fmaf(a.y, kv.x, s[1][0]); s[1][1] = fmaf(a.y, kv.y, s[1][1]);
            s[1][2] = fmaf(a.y, kv.z, s[1][2]); s[1][3] = fmaf(a.y, kv.w, s[1][3]);
            s[2][0] = fmaf(a.z, kv.x, s[2][0]); s[2][1] = fmaf(a.z, kv.y, s[2][1]);
            s[2][2] = fmaf(a.z, kv.z, s[2][2]); s[2][3] = fmaf(a.z, kv.w, s[2][3]);
            s[3][0] = fmaf(a.w, kv.x, s[3][0]); s[3][1] = fmaf(a.w, kv.y, s[3][1]);
            s[3][2] = fmaf(a.w, kv.z, s[3][2]); s[3][3] = fmaf(a.w, kv.w, s[3][3]);
        }
#pragma unroll
        for (int j = 0; j < 4; j++)
            *(float4*)(Pt + (kb + j) * 68 + qq) =
                make_float4(s[0][j], s[1][j], s[2][j], s[3][j]);
        __syncthreads();

        if (tid < 64) {
            const int q = tid;
            const float mo = m_s[q];
            float mx = mo;
#pragma unroll 8
            for (int kk = 0; kk < 64; kk++) mx = fmaxf(mx, Pt[kk * 68 + q]);
            const float corr = __expf(mo - mx);
            float l = l_s[q] * corr;
#pragma unroll 8
            for (int kk = 0; kk < 64; kk++) {
                const float p = __expf(Pt[kk * 68 + q] - mx);
                Pt[kk * 68 + q] = p;
                l += p;
            }
            m_s[q] = mx; l_s[q] = l; corr_s[q] = corr;
        }
        __syncthreads();

        {
            const float c0 = corr_s[qq + 0], c1 = corr_s[qq + 1];
            const float c2 = corr_s[qq + 2], c3 = corr_s[qq + 3];
#pragma unroll
            for (int j = 0; j < 4; j++) {
                acc[0][j] *= c0; acc[1][j] *= c1;
                acc[2][j] *= c2; acc[3][j] *= c3;
            }
        }
#pragma unroll 8
        for (int kk = 0; kk < 64; kk++) {
            const float4 p = *(const float4*)(Pt + kk * 68 + qq);
            const float4 v = *(const float4*)(Vs + kk * 68 + hb);
            acc[0][0] = fmaf(p.x, v.x, acc[0][0]); acc[0][1] = fmaf(p.x, v.y, acc[0][1]);
            acc[0][2] = fmaf(p.x, v.z, acc[0][2]); acc[0][3] = fmaf(p.x, v.w, acc[0][3]);
            acc[1][0] = fmaf(p.y, v.x, acc[1][0]); acc[1][1] = fmaf(p.y, v.y, acc[1][1]);
            acc[1][2] = fmaf(p.y, v.z, acc[1][2]); acc[1][3] = fmaf(p.y, v.w, acc[1][3]);
            acc[2][0] = fmaf(p.z, v.x, acc[2][0]); acc[2][1] = fmaf(p.z, v.y, acc[2][1]);
            acc[2][2] = fmaf(p.z, v.z, acc[2][2]); acc[2][3] = fmaf(p.z, v.w, acc[2][3]);
            acc[3][0] = fmaf(p.w, v.x, acc[3][0]); acc[3][1] = fmaf(p.w, v.y, acc[3][1]);
            acc[3][2] = fmaf(p.w, v.z, acc[3][2]); acc[3][3] = fmaf(p.w, v.w, acc[3][3]);
        }
        __syncthreads();
    }

    float inv[4];
#pragma unroll
    for (int i = 0; i < 4; i++) inv[i] = 1.f / l_s[qq + i];

    float* Cg = g_C + ((size_t)b * SS + q0g) * DD + h * HDD;
#pragma unroll
    for (int i = 0; i < 4; i++) {
        const float4 o = make_float4(acc[i][0] * inv[i], acc[i][1] * inv[i],
                                     acc[i][2] * inv[i], acc[i][3] * inv[i]);
        *(float4*)(Cg + (size_t)(qq + i) * DD + hb) = o;
    }
}

// ---------------------------------------------------------------------------
// Launch: QKV tf32 GEMMs -> flash attention -> tf32 output projection
// ---------------------------------------------------------------------------
extern "C" void kernel_launch(void* const* d_in, const int* in_sizes, int n_in,
                              void* d_out, int out_size)
{
    (void)in_sizes; (void)n_in; (void)out_size;
    const float* x  = (const float*)d_in[0];
    const float* Wq = (const float*)d_in[1];
    const float* bq = (const float*)d_in[2];
    const float* Wk = (const float*)d_in[3];
    const float* bk = (const float*)d_in[4];
    const float* Wv = (const float*)d_in[5];
    const float* bv = (const float*)d_in[6];
    const float* Wo = (const float*)d_in[7];
    const float* bo = (const float*)d_in[8];
    float* out = (float*)d_out;

    float *qp, *kp, *vp, *cp;
    cudaGetSymbolAddress((void**)&qp, g_Q);
    cudaGetSymbolAddress((void**)&kp, g_K);
    cudaGetSymbolAddress((void**)&vp, g_V);
    cudaGetSymbolAddress((void**)&cp, g_C);

    cudaFuncSetAttribute(attn_kernel,
                         cudaFuncAttributeMaxDynamicSharedMemorySize,
                         ATT_SMEM_BYTES);

    const dim3 gblk(256);
    const dim3 ggrid(DD / 128, MROWS / 128);   // (8, 32)

    gemm_tf32<<<ggrid, gblk>>>(x, Wq, bq, qp);
    gemm_tf32<<<ggrid, gblk>>>(x, Wk, bk, kp);
    gemm_tf32<<<ggrid, gblk>>>(x, Wv, bv, vp);

    attn_kernel<<<dim3(SS / 64, HH, BB), 256, ATT_SMEM_BYTES>>>();

    gemm_tf32<<<ggrid, gblk>>>(cp, Wo, bo, out);
}

// round 4
// speedup vs baseline: 2.0972x; 1.6581x over previous
#include <cuda_runtime.h>
#include <cstdint>

// Problem constants: B=2, S=2048, D=1024, H=16, HD=64
#define BB 2
#define SS 2048
#define DD 1024
#define HH 16
#define HDD 64
#define MROWS (BB * SS)   // 4096

__device__ float g_Q[BB * SS * DD];
__device__ float g_K[BB * SS * DD];
__device__ float g_V[BB * SS * DD];
__device__ float g_C[BB * SS * DD];

// ---------------------------------------------------------------------------
// tf32 helpers
// ---------------------------------------------------------------------------
__device__ __forceinline__ uint32_t f2tf32(float x) {
    uint32_t u;
    asm("cvt.rna.tf32.f32 %0, %1;" : "=r"(u) : "f"(x));
    return u;
}
__device__ __forceinline__ float tf32f(float x) {
    return __uint_as_float(f2tf32(x));
}

#define MMA_TF32(d, a, b)                                                    \
    asm volatile(                                                            \
        "mma.sync.aligned.m16n8k8.row.col.f32.tf32.tf32.f32 "                \
        "{%0,%1,%2,%3}, {%4,%5,%6,%7}, {%8,%9}, {%0,%1,%2,%3};"              \
        : "+f"((d)[0]), "+f"((d)[1]), "+f"((d)[2]), "+f"((d)[3])             \
        : "r"((a)[0]), "r"((a)[1]), "r"((a)[2]), "r"((a)[3]),                \
          "r"((b)[0]), "r"((b)[1]))

// ---------------------------------------------------------------------------
// tf32 tensor-core GEMM (verified round 2, unchanged)
// ---------------------------------------------------------------------------
#define AST 18

__global__ __launch_bounds__(256, 2)
void gemm_tf32(const float* __restrict__ A, const float* __restrict__ W,
               const float* __restrict__ bias, float* __restrict__ C)
{
    constexpr int K = 1024, N = 1024;
    __shared__ float As[128][AST];
    __shared__ float Bs[128][AST];

    const int tid  = threadIdx.x;
    const int lane = tid & 31;
    const int wid  = tid >> 5;
    const int warp_m = wid >> 2;
    const int warp_n = wid & 3;
    const int rowBase = blockIdx.y * 128;
    const int colBase = blockIdx.x * 128;

    const int arow = tid >> 1;
    const int ag   = tid & 1;
    const int brow = tid >> 4;
    const int bcol = (tid & 15) * 4;

    const float* Ap = A + (size_t)(rowBase + arow) * K + ag * 8;
    const float* Wp = W + (size_t)brow * N + colBase + bcol;

    const int bg = brow >> 3;
    const int bp = 2 * (brow & 3) + (((brow & 7) >= 4) ? 1 : 0);
    const int bc = bg * 8 + bp;

    float acc[4][4][4];
#pragma unroll
    for (int mt = 0; mt < 4; mt++)
#pragma unroll
        for (int nt = 0; nt < 4; nt++)
#pragma unroll
            for (int r = 0; r < 4; r++) acc[mt][nt][r] = 0.f;

    float4 a0v = *(const float4*)(Ap);
    float4 a1v = *(const float4*)(Ap + 4);
    float4 b0v = *(const float4*)(Wp);
    float4 b1v = *(const float4*)(Wp + 64);

    {
        const int c0 = ag * 8;
        As[arow][c0 + 0] = tf32f(a0v.x);
        As[arow][c0 + 2] = tf32f(a0v.y);
        As[arow][c0 + 4] = tf32f(a0v.z);
        As[arow][c0 + 6] = tf32f(a0v.w);
        As[arow][c0 + 1] = tf32f(a1v.x);
        As[arow][c0 + 3] = tf32f(a1v.y);
        As[arow][c0 + 5] = tf32f(a1v.z);
        As[arow][c0 + 7] = tf32f(a1v.w);
        Bs[bcol + 0][bc] = tf32f(b0v.x);
        Bs[bcol + 1][bc] = tf32f(b0v.y);
        Bs[bcol + 2][bc] = tf32f(b0v.z);
        Bs[bcol + 3][bc] = tf32f(b0v.w);
        Bs[bcol + 64][bc] = tf32f(b1v.x);
        Bs[bcol + 65][bc] = tf32f(b1v.y);
        Bs[bcol + 66][bc] = tf32f(b1v.z);
        Bs[bcol + 67][bc] = tf32f(b1v.w);
    }
    __syncthreads();

    const int niter = K / 16;
    for (int kt = 0; kt < niter; kt++) {
        if (kt + 1 < niter) {
            const int ko = (kt + 1) * 16;
            a0v = *(const float4*)(Ap + ko);
            a1v = *(const float4*)(Ap + ko + 4);
            b0v = *(const float4*)(Wp + (size_t)ko * N);
            b1v = *(const float4*)(Wp + (size_t)ko * N + 64);
        }

#pragma unroll
        for (int s = 0; s < 2; s++) {
            uint32_t af[4][4];
            uint32_t bf[4][2];
            const int kc = s * 8 + 2 * (lane & 3);
#pragma unroll
            for (int mt = 0; mt < 4; mt++) {
                const int r = warp_m * 64 + mt * 16 + (lane >> 2);
                const float2 lo = *(const float2*)&As[r][kc];
                const float2 hi = *(const float2*)&As[r + 8][kc];
                af[mt][0] = __float_as_uint(lo.x);
                af[mt][2] = __float_as_uint(lo.y);
                af[mt][1] = __float_as_uint(hi.x);
                af[mt][3] = __float_as_uint(hi.y);
            }
#pragma unroll
            for (int nt = 0; nt < 4; nt++) {
                const int n = warp_n * 32 + nt * 8 + (lane >> 2);
                const float2 bb = *(const float2*)&Bs[n][kc];
                bf[nt][0] = __float_as_uint(bb.x);
                bf[nt][1] = __float_as_uint(bb.y);
            }
#pragma unroll
            for (int mt = 0; mt < 4; mt++)
#pragma unroll
                for (int nt = 0; nt < 4; nt++)
                    MMA_TF32(acc[mt][nt], af[mt], bf[nt]);
        }

        if (kt + 1 < niter) {
            __syncthreads();
            const int c0 = ag * 8;
            As[arow][c0 + 0] = tf32f(a0v.x);
            As[arow][c0 + 2] = tf32f(a0v.y);
            As[arow][c0 + 4] = tf32f(a0v.z);
            As[arow][c0 + 6] = tf32f(a0v.w);
            As[arow][c0 + 1] = tf32f(a1v.x);
            As[arow][c0 + 3] = tf32f(a1v.y);
            As[arow][c0 + 5] = tf32f(a1v.z);
            As[arow][c0 + 7] = tf32f(a1v.w);
            Bs[bcol + 0][bc] = tf32f(b0v.x);
            Bs[bcol + 1][bc] = tf32f(b0v.y);
            Bs[bcol + 2][bc] = tf32f(b0v.z);
            Bs[bcol + 3][bc] = tf32f(b0v.w);
            Bs[bcol + 64][bc] = tf32f(b1v.x);
            Bs[bcol + 65][bc] = tf32f(b1v.y);
            Bs[bcol + 66][bc] = tf32f(b1v.z);
            Bs[bcol + 67][bc] = tf32f(b1v.w);
            __syncthreads();
        }
    }

#pragma unroll
    for (int mt = 0; mt < 4; mt++) {
        const int r = rowBase + warp_m * 64 + mt * 16 + (lane >> 2);
#pragma unroll
        for (int nt = 0; nt < 4; nt++) {
            const int c = colBase + warp_n * 32 + nt * 8 + (lane & 3) * 2;
            const float bi0 = bias[c], bi1 = bias[c + 1];
            float2 o0 = make_float2(acc[mt][nt][0] + bi0, acc[mt][nt][1] + bi1);
            float2 o1 = make_float2(acc[mt][nt][2] + bi0, acc[mt][nt][3] + bi1);
            *(float2*)&C[(size_t)r * N + c] = o0;
            *(float2*)&C[(size_t)(r + 8) * N + c] = o1;
        }
    }
}

// ---------------------------------------------------------------------------
// Tensor-core flash attention (tf32).
// CTA = (b, h, 128-query tile). 8 warps; warp w owns q rows [16w, 16w+16).
// K tile 128 keys per iteration, 16 iterations over S=2048.
//
// smem (dynamic):
//   Ksm [128 keys][72]  : K tile, row = key, col = perm(d)   (36,864 B)
//   Vt  [64 d]   [136]  : V tile transposed, col = perm(key) (34,816 B)
//   Psm [128 q]  [136]  : probs in A-frag perm layout; also Q staging (69,632 B)
// perm within each 8-group: pos(j) = 2*(j&3) + (j>>2)  -> A/B fragment pair
// (k, k+4) is adjacent => single LDS.64.
// ---------------------------------------------------------------------------
#define PKS 72
#define PVS 136
#define PPS 136
#define ATT_SMEM_BYTES ((128 * PKS + 64 * PVS + 128 * PPS) * 4)  // 141,312

__global__ __launch_bounds__(256, 1)
void attn_tc()
{
    extern __shared__ float sm[];
    float* Ksm = sm;                          // [128][PKS]
    float* Vt  = sm + 128 * PKS;              // [64][PVS]
    float* Psm = sm + 128 * PKS + 64 * PVS;   // [128][PPS]

    const int tid  = threadIdx.x;
    const int lane = tid & 31;
    const int w    = tid >> 5;
    const int b = blockIdx.z, h = blockIdx.y;
    const int q0 = blockIdx.x * 128;

    const float* Qg = g_Q + ((size_t)b * SS + q0) * DD + h * HDD;
    const float* Kg = g_K + (size_t)b * SS * DD + h * HDD;
    const float* Vg = g_V + (size_t)b * SS * DD + h * HDD;

    // global tile-load mapping: thread handles row tid>>1, one 32-wide d half
    const int grow = tid >> 1;
    const int gcb  = (tid & 1) * 32;

    // ---- stage Q into Psm (perm layout), pre-scaled by 1/sqrt(HD) ----
#pragma unroll
    for (int c = 0; c < 8; c++) {
        const int d0 = gcb + c * 4;                 // multiple of 4
        const float4 v = *(const float4*)(Qg + (size_t)grow * DD + d0);
        const int g   = d0 >> 3;
        const int off = (d0 & 4) ? 1 : 0;
        float* p = Psm + grow * PPS + g * 8 + off;
        p[0] = tf32f(v.x * 0.125f);
        p[2] = tf32f(v.y * 0.125f);
        p[4] = tf32f(v.z * 0.125f);
        p[6] = tf32f(v.w * 0.125f);
    }
    __syncthreads();

    // ---- load Q A-fragments (warp-private rows) ----
    const int r = w * 16 + (lane >> 2);         // this thread's q row (and r+8)
    const int kc = 2 * (lane & 3);
    uint32_t qf[8][4];
#pragma unroll
    for (int s = 0; s < 8; s++) {
        const float2 lo = *(const float2*)&Psm[r * PPS + s * 8 + kc];
        const float2 hi = *(const float2*)&Psm[(r + 8) * PPS + s * 8 + kc];
        qf[s][0] = __float_as_uint(lo.x);
        qf[s][1] = __float_as_uint(hi.x);
        qf[s][2] = __float_as_uint(lo.y);
        qf[s][3] = __float_as_uint(hi.y);
    }

    // online softmax state (rows r and r+8)
    float m0 = -1e30f, m1 = -1e30f, l0 = 0.f, l1 = 0.f;
    float oacc[8][4];
#pragma unroll
    for (int nt = 0; nt < 8; nt++)
#pragma unroll
        for (int i = 0; i < 4; i++) oacc[nt][i] = 0.f;

    const int pc0 = 2 * (kc & 3) + (kc >> 2);          // perm(2*(lane&3))
    const int pc1 = 2 * ((kc + 1) & 3) + ((kc + 1) >> 2);

    for (int kt = 0; kt < SS / 128; kt++) {
        const int kr = kt * 128;
        __syncthreads();   // prev iteration's K/V reads complete

        // ---- load K tile -> Ksm[key][perm(d)] ----
#pragma unroll
        for (int c = 0; c < 8; c++) {
            const int d0 = gcb + c * 4;
            const float4 v = *(const float4*)(Kg + (size_t)(kr + grow) * DD + d0);
            const int g   = d0 >> 3;
            const int off = (d0 & 4) ? 1 : 0;
            float* p = Ksm + grow * PKS + g * 8 + off;
            p[0] = tf32f(v.x);
            p[2] = tf32f(v.y);
            p[4] = tf32f(v.z);
            p[6] = tf32f(v.w);
        }
        // ---- load V tile -> Vt[d][perm(key)] (transpose) ----
        {
            const int key = grow;
            const int kp  = (key & ~7) + 2 * (key & 3) + ((key & 7) >> 2);
#pragma unroll
            for (int c = 0; c < 8; c++) {
                const int d0 = gcb + c * 4;
                const float4 v = *(const float4*)(Vg + (size_t)(kr + key) * DD + d0);
                Vt[(d0 + 0) * PVS + kp] = tf32f(v.x);
                Vt[(d0 + 1) * PVS + kp] = tf32f(v.y);
                Vt[(d0 + 2) * PVS + kp] = tf32f(v.z);
                Vt[(d0 + 3) * PVS + kp] = tf32f(v.w);
            }
        }
        __syncthreads();

        // ---- scores: S[16 q][128 key] per warp ----
        float sacc[16][4];
#pragma unroll
        for (int nt = 0; nt < 16; nt++)
#pragma unroll
            for (int i = 0; i < 4; i++) sacc[nt][i] = 0.f;

#pragma unroll
        for (int s = 0; s < 8; s++) {
#pragma unroll
            for (int nt = 0; nt < 16; nt++) {
                const float2 bv =
                    *(const float2*)&Ksm[(nt * 8 + (lane >> 2)) * PKS + s * 8 + kc];
                uint32_t bf[2] = {__float_as_uint(bv.x), __float_as_uint(bv.y)};
                MMA_TF32(sacc[nt], qf[s], bf);
            }
        }

        // ---- online softmax (rows r, r+8; quad shfl reductions) ----
        float tm0 = -1e30f, tm1 = -1e30f;
#pragma unroll
        for (int nt = 0; nt < 16; nt++) {
            tm0 = fmaxf(tm0, fmaxf(sacc[nt][0], sacc[nt][1]));
            tm1 = fmaxf(tm1, fmaxf(sacc[nt][2], sacc[nt][3]));
        }
        tm0 = fmaxf(tm0, __shfl_xor_sync(0xffffffffu, tm0, 1));
        tm0 = fmaxf(tm0, __shfl_xor_sync(0xffffffffu, tm0, 2));
        tm1 = fmaxf(tm1, __shfl_xor_sync(0xffffffffu, tm1, 1));
        tm1 = fmaxf(tm1, __shfl_xor_sync(0xffffffffu, tm1, 2));

        const float nm0 = fmaxf(m0, tm0);
        const float nm1 = fmaxf(m1, tm1);
        const float cr0 = __expf(m0 - nm0);
        const float cr1 = __expf(m1 - nm1);

        float s0 = 0.f, s1 = 0.f;
#pragma unroll
        for (int nt = 0; nt < 16; nt++) {
            const float p00 = __expf(sacc[nt][0] - nm0);
            const float p01 = __expf(sacc[nt][1] - nm0);
            const float p10 = __expf(sacc[nt][2] - nm1);
            const float p11 = __expf(sacc[nt][3] - nm1);
            s0 += p00 + p01;
            s1 += p10 + p11;
            Psm[r * PPS + nt * 8 + pc0]       = tf32f(p00);
            Psm[r * PPS + nt * 8 + pc1]       = tf32f(p01);
            Psm[(r + 8) * PPS + nt * 8 + pc0] = tf32f(p10);
            Psm[(r + 8) * PPS + nt * 8 + pc1] = tf32f(p11);
        }
        s0 += __shfl_xor_sync(0xffffffffu, s0, 1);
        s0 += __shfl_xor_sync(0xffffffffu, s0, 2);
        s1 += __shfl_xor_sync(0xffffffffu, s1, 1);
        s1 += __shfl_xor_sync(0xffffffffu, s1, 2);

        l0 = l0 * cr0 + s0;
        l1 = l1 * cr1 + s1;
        m0 = nm0;
        m1 = nm1;

#pragma unroll
        for (int nt = 0; nt < 8; nt++) {
            oacc[nt][0] *= cr0; oacc[nt][1] *= cr0;
            oacc[nt][2] *= cr1; oacc[nt][3] *= cr1;
        }
        __syncwarp();   // P rows are warp-private: order STS -> LDS in-warp

        // ---- PV: O[16 q][64 d] += P[16 q][128 key] @ V[128 key][64 d] ----
#pragma unroll
        for (int s2 = 0; s2 < 16; s2++) {
            const float2 plo = *(const float2*)&Psm[r * PPS + s2 * 8 + kc];
            const float2 phi = *(const float2*)&Psm[(r + 8) * PPS + s2 * 8 + kc];
            uint32_t pf[4];
            pf[0] = __float_as_uint(plo.x);
            pf[1] = __float_as_uint(phi.x);
            pf[2] = __float_as_uint(plo.y);
            pf[3] = __float_as_uint(phi.y);
#pragma unroll
            for (int nt = 0; nt < 8; nt++) {
                const float2 bv =
                    *(const float2*)&Vt[(nt * 8 + (lane >> 2)) * PVS + s2 * 8 + kc];
                uint32_t bf[2] = {__float_as_uint(bv.x), __float_as_uint(bv.y)};
                MMA_TF32(oacc[nt], pf, bf);
            }
        }
    }

    // ---- finalize: /l, write ctx ----
    const float inv0 = 1.f / l0;
    const float inv1 = 1.f / l1;
    float* Cg0 = g_C + ((size_t)b * SS + q0 + r) * DD + h * HDD;
    float* Cg1 = g_C + ((size_t)b * SS + q0 + r + 8) * DD + h * HDD;
#pragma unroll
    for (int nt = 0; nt < 8; nt++) {
        const int c = nt * 8 + kc;
        *(float2*)&Cg0[c] = make_float2(oacc[nt][0] * inv0, oacc[nt][1] * inv0);
        *(float2*)&Cg1[c] = make_float2(oacc[nt][2] * inv1, oacc[nt][3] * inv1);
    }
}

// ---------------------------------------------------------------------------
// Launch
// ---------------------------------------------------------------------------
extern "C" void kernel_launch(void* const* d_in, const int* in_sizes, int n_in,
                              void* d_out, int out_size)
{
    (void)in_sizes; (void)n_in; (void)out_size;
    const float* x  = (const float*)d_in[0];
    const float* Wq = (const float*)d_in[1];
    const float* bq = (const float*)d_in[2];
    const float* Wk = (const float*)d_in[3];
    const float* bk = (const float*)d_in[4];
    const float* Wv = (const float*)d_in[5];
    const float* bv = (const float*)d_in[6];
    const float* Wo = (const float*)d_in[7];
    const float* bo = (const float*)d_in[8];
    float* out = (float*)d_out;

    float *qp, *kp, *vp, *cp;
    cudaGetSymbolAddress((void**)&qp, g_Q);
    cudaGetSymbolAddress((void**)&kp, g_K);
    cudaGetSymbolAddress((void**)&vp, g_V);
    cudaGetSymbolAddress((void**)&cp, g_C);

    cudaFuncSetAttribute(attn_tc,
                         cudaFuncAttributeMaxDynamicSharedMemorySize,
                         ATT_SMEM_BYTES);

    const dim3 gblk(256);
    const dim3 ggrid(DD / 128, MROWS / 128);   // (8, 32)

    gemm_tf32<<<ggrid, gblk>>>(x, Wq, bq, qp);
    gemm_tf32<<<ggrid, gblk>>>(x, Wk, bk, kp);
    gemm_tf32<<<ggrid, gblk>>>(x, Wv, bv, vp);

    attn_tc<<<dim3(SS / 128, HH, BB), 256, ATT_SMEM_BYTES>>>();

    gemm_tf32<<<ggrid, gblk>>>(cp, Wo, bo, out);
}